// round 7
// baseline (speedup 1.0000x reference)
#include <cuda_runtime.h>
#include <cstdint>

#define NN 8192
#define EE 1024
#define FF 256
#define NW (NN/32)   // 256 words per edge row (transposed bits)
#define EW (EE/32)   // 32 words per node row

// ---- scratch (no allocations allowed; device globals) ----
__device__ float    g_dvis[NN];                     // dv^{-1/2}
__device__ unsigned g_HbT[EE * NW];                 // H^T bitpacked: [edge][node-word]
__device__ unsigned g_HbR[NN * EW];                 // H bitpacked:   [node][edge-word]
__device__ __align__(16) float g_M [EE * FF];       // edge features (De^-1 H^T Dv^-1/2 X)
__device__ __align__(16) float g_MW[EE * FF];       // M @ W^T

// ============================================================
// One-pass pack: coalesced read of H, produces HbR, HbT (via
// in-warp bit transpose) and dv^{-1/2}. CTA = 32 rows x 1024 cols.
// ============================================================
__global__ void __launch_bounds__(256) pack_all(const float* __restrict__ H) {
    const int r0 = blockIdx.x * 32;
    const int w  = threadIdx.x >> 5;
    const int l  = threadIdx.x & 31;

    __shared__ unsigned smask[32][32];   // [col-chunk][row]

    int cnt[4] = {0, 0, 0, 0};
    for (int ch = 0; ch < 32; ++ch) {
        const int c0 = ch * 32;
        #pragma unroll
        for (int k = 0; k < 4; ++k) {
            const int row = w + 8 * k;
            float v = H[(long)(r0 + row) * EE + c0 + l];   // coalesced
            unsigned m = __ballot_sync(0xffffffffu, v != 0.f);
            cnt[k] += __popc(m);
            if (l == 0) {
                smask[ch][row] = m;
                g_HbR[(r0 + row) * EW + ch] = m;
            }
        }
    }
    if (l == 0) {
        #pragma unroll
        for (int k = 0; k < 4; ++k)
            g_dvis[r0 + w + 8 * k] = rsqrtf((float)cnt[k]);
    }
    __syncthreads();

    const int wordIdx = blockIdx.x;
    #pragma unroll
    for (int q = 0; q < 4; ++q) {
        const int cc = w + 8 * q;
        const unsigned rm = smask[cc][l];
        #pragma unroll
        for (int c = 0; c < 32; ++c) {
            unsigned colm = __ballot_sync(0xffffffffu, (rm >> c) & 1u);
            if (l == 0) g_HbT[(cc * 32 + c) * NW + wordIdx] = colm;
        }
    }
}

// ============================================================
// Pass A: M[e] = (1/de) * sum_{i in e} dvis[i] * X[i]
// one CTA per edge. 4 row-groups x 64 threads own CONTIGUOUS row
// blocks; 8 indices loaded as one uint4, 8 scales as 2 float4.
// ============================================================
#define MAX_DE 1024
__global__ void __launch_bounds__(256) edge_gather(const float* __restrict__ X) {
    const int e = blockIdx.x;
    const int t = threadIdx.x;
    const int lane = t & 31, wid = t >> 5;
    const int f = t & 63;          // float4 column
    const int g = t >> 6;          // row group 0..3

    __shared__ __align__(16) unsigned short sidx[MAX_DE];
    __shared__ __align__(16) float          sdvv[MAX_DE];
    __shared__ int wtot[8];
    __shared__ int warpOff[9];
    __shared__ float4 red[256];

    // ---- extract node indices (deterministic order) ----
    unsigned m = g_HbT[e * NW + t];
    int cnt = __popc(m);
    int scan = cnt;
    #pragma unroll
    for (int o = 1; o < 32; o <<= 1) {
        int v = __shfl_up_sync(0xffffffffu, scan, o);
        if (lane >= o) scan += v;
    }
    if (lane == 31) wtot[wid] = scan;
    __syncthreads();
    if (t == 0) {
        int s = 0;
        #pragma unroll
        for (int w = 0; w < 8; ++w) { warpOff[w] = s; s += wtot[w]; }
        warpOff[8] = s;
    }
    __syncthreads();

    int off = warpOff[wid] + (scan - cnt);
    const int base = t * 32;
    while (m) {
        int b = __ffs(m) - 1;
        m &= m - 1;
        int node = base + b;
        sidx[off] = (unsigned short)node;
        sdvv[off] = g_dvis[node];
        ++off;
    }
    __syncthreads();

    // ---- gather: contiguous block per group, 8-aligned ----
    const int total = warpOff[8];
    const int Q  = ((total + 31) >> 5) << 3;   // ceil(total/4) rounded to 8
    const int jb = g * Q;
    const int je = min(jb + Q, total);

    const float4* X4 = (const float4*)X;
    float4 acc = make_float4(0.f, 0.f, 0.f, 0.f);

    int j = jb;
    for (; j + 8 <= je; j += 8) {
        uint4  iw = *(const uint4*)&sidx[j];           // 8 node indices
        float4 sa = *(const float4*)&sdvv[j];          // 4 scales
        float4 sb = *(const float4*)&sdvv[j + 4];      // 4 scales
        int n0 = iw.x & 0xffff, n1 = iw.x >> 16;
        int n2 = iw.y & 0xffff, n3 = iw.y >> 16;
        int n4 = iw.z & 0xffff, n5 = iw.z >> 16;
        int n6 = iw.w & 0xffff, n7 = iw.w >> 16;
        float4 x0 = X4[n0 * 64 + f];
        float4 x1 = X4[n1 * 64 + f];
        float4 x2 = X4[n2 * 64 + f];
        float4 x3 = X4[n3 * 64 + f];
        float4 x4 = X4[n4 * 64 + f];
        float4 x5 = X4[n5 * 64 + f];
        float4 x6 = X4[n6 * 64 + f];
        float4 x7 = X4[n7 * 64 + f];
        acc.x = fmaf(x0.x, sa.x, acc.x); acc.y = fmaf(x0.y, sa.x, acc.y);
        acc.z = fmaf(x0.z, sa.x, acc.z); acc.w = fmaf(x0.w, sa.x, acc.w);
        acc.x = fmaf(x1.x, sa.y, acc.x); acc.y = fmaf(x1.y, sa.y, acc.y);
        acc.z = fmaf(x1.z, sa.y, acc.z); acc.w = fmaf(x1.w, sa.y, acc.w);
        acc.x = fmaf(x2.x, sa.z, acc.x); acc.y = fmaf(x2.y, sa.z, acc.y);
        acc.z = fmaf(x2.z, sa.z, acc.z); acc.w = fmaf(x2.w, sa.z, acc.w);
        acc.x = fmaf(x3.x, sa.w, acc.x); acc.y = fmaf(x3.y, sa.w, acc.y);
        acc.z = fmaf(x3.z, sa.w, acc.z); acc.w = fmaf(x3.w, sa.w, acc.w);
        acc.x = fmaf(x4.x, sb.x, acc.x); acc.y = fmaf(x4.y, sb.x, acc.y);
        acc.z = fmaf(x4.z, sb.x, acc.z); acc.w = fmaf(x4.w, sb.x, acc.w);
        acc.x = fmaf(x5.x, sb.y, acc.x); acc.y = fmaf(x5.y, sb.y, acc.y);
        acc.z = fmaf(x5.z, sb.y, acc.z); acc.w = fmaf(x5.w, sb.y, acc.w);
        acc.x = fmaf(x6.x, sb.z, acc.x); acc.y = fmaf(x6.y, sb.z, acc.y);
        acc.z = fmaf(x6.z, sb.z, acc.z); acc.w = fmaf(x6.w, sb.z, acc.w);
        acc.x = fmaf(x7.x, sb.w, acc.x); acc.y = fmaf(x7.y, sb.w, acc.y);
        acc.z = fmaf(x7.z, sb.w, acc.z); acc.w = fmaf(x7.w, sb.w, acc.w);
    }
    for (; j < je; ++j) {
        int n = sidx[j]; float s = sdvv[j];
        float4 x = X4[n * 64 + f];
        acc.x = fmaf(x.x, s, acc.x); acc.y = fmaf(x.y, s, acc.y);
        acc.z = fmaf(x.z, s, acc.z); acc.w = fmaf(x.w, s, acc.w);
    }

    red[t] = acc;
    __syncthreads();
    if (g == 0) {
        float4 a = red[f], b = red[f + 64], c = red[f + 128], d = red[f + 192];
        float di = 1.f / (float)total;
        float4 o;
        o.x = (a.x + b.x + c.x + d.x) * di;
        o.y = (a.y + b.y + c.y + d.y) * di;
        o.z = (a.z + b.z + c.z + d.z) * di;
        o.w = (a.w + b.w + c.w + d.w) * di;
        *(float4*)&g_M[e * FF + f * 4] = o;
    }
}

// ============================================================
// g_MW = g_M @ W^T   ([1024,256] @ [256,256], both K-major)
// ============================================================
__global__ void __launch_bounds__(256) gemm_mw(const float* __restrict__ Wm) {
    __shared__ float As[32][128];
    __shared__ float Bs[32][64];

    const int tid = threadIdx.x;
    const int ty = tid >> 4;
    const int tx = tid & 15;
    const int i0 = blockIdx.y * 128;
    const int o0 = blockIdx.x * 64;

    float acc[8][4];
    #pragma unroll
    for (int r = 0; r < 8; ++r)
        #pragma unroll
        for (int c = 0; c < 4; ++c) acc[r][c] = 0.f;

    for (int kc = 0; kc < FF; kc += 32) {
        #pragma unroll
        for (int l = 0; l < 4; ++l) {
            int linear = tid + 256 * l;
            int i  = linear >> 3;
            int kq = (linear & 7) << 2;
            float4 v = *(const float4*)&g_M[(i0 + i) * FF + kc + kq];
            As[kq + 0][i] = v.x; As[kq + 1][i] = v.y;
            As[kq + 2][i] = v.z; As[kq + 3][i] = v.w;
        }
        #pragma unroll
        for (int l = 0; l < 2; ++l) {
            int linear = tid + 256 * l;
            int o  = linear >> 3;
            int kq = (linear & 7) << 2;
            float4 v = *(const float4*)&Wm[(o0 + o) * FF + kc + kq];
            Bs[kq + 0][o] = v.x; Bs[kq + 1][o] = v.y;
            Bs[kq + 2][o] = v.z; Bs[kq + 3][o] = v.w;
        }
        __syncthreads();
        #pragma unroll
        for (int kk = 0; kk < 32; ++kk) {
            float4 b4 = *(const float4*)&Bs[kk][tx * 4];
            float4 a0 = *(const float4*)&As[kk][ty * 8];
            float4 a1 = *(const float4*)&As[kk][ty * 8 + 4];
            float a[8] = {a0.x, a0.y, a0.z, a0.w, a1.x, a1.y, a1.z, a1.w};
            float bb[4] = {b4.x, b4.y, b4.z, b4.w};
            #pragma unroll
            for (int r = 0; r < 8; ++r)
                #pragma unroll
                for (int c = 0; c < 4; ++c)
                    acc[r][c] = fmaf(a[r], bb[c], acc[r][c]);
        }
        __syncthreads();
    }

    #pragma unroll
    for (int r = 0; r < 8; ++r) {
        int i = i0 + ty * 8 + r;
        float4 o4;
        o4.x = acc[r][0]; o4.y = acc[r][1];
        o4.z = acc[r][2]; o4.w = acc[r][3];
        *(float4*)&g_MW[i * FF + o0 + tx * 4] = o4;
    }
}

// ============================================================
// Pass B (fused epilogue): out[i] = dvis[i] * sum_{e ni i} MW[e] + b
// TWO nodes per CTA; 2 contiguous row-blocks x 64 threads per node;
// 8 indices per uint4 LDS.128.
// ============================================================
#define MAX_DV 128
__global__ void __launch_bounds__(256) node_gather(const float* __restrict__ bias,
                                                   float* __restrict__ out) {
    const int t    = threadIdx.x;
    const int half = t >> 7;           // 0 or 1
    const int ht   = t & 127;          // id within half
    const int i    = blockIdx.x * 2 + half;
    const int f    = ht & 63;          // float4 column
    const int g    = ht >> 6;          // row block 0/1

    __shared__ __align__(16) unsigned short sidx[2][MAX_DV];
    __shared__ int stot[2];
    __shared__ float4 red[256];

    // decode: warp 0 handles half=0, warp 4 handles half=1
    if (ht < 32) {
        unsigned m = g_HbR[i * EW + ht];
        int cnt = __popc(m);
        int scan = cnt;
        #pragma unroll
        for (int o = 1; o < 32; o <<= 1) {
            int v = __shfl_up_sync(0xffffffffu, scan, o);
            if (ht >= o) scan += v;
        }
        int off = scan - cnt;
        const int base = ht * 32;
        while (m) {
            int b = __ffs(m) - 1;
            m &= m - 1;
            sidx[half][off++] = (unsigned short)(base + b);
        }
        if (ht == 31) stot[half] = scan;
    }
    __syncthreads();

    const int total = stot[half];
    const int Q  = ((total + 15) >> 4) << 3;   // ceil(total/2) rounded to 8
    const int jb = g * Q;
    const int je = min(jb + Q, total);

    const unsigned short* idx = sidx[half];
    const float4* M4 = (const float4*)g_MW;
    float4 acc = make_float4(0.f, 0.f, 0.f, 0.f);

    int j = jb;
    for (; j + 8 <= je; j += 8) {
        uint4 iw = *(const uint4*)&idx[j];             // 8 edge indices
        int e0 = iw.x & 0xffff, e1 = iw.x >> 16;
        int e2 = iw.y & 0xffff, e3 = iw.y >> 16;
        int e4 = iw.z & 0xffff, e5 = iw.z >> 16;
        int e6 = iw.w & 0xffff, e7 = iw.w >> 16;
        float4 x0 = M4[e0 * 64 + f];
        float4 x1 = M4[e1 * 64 + f];
        float4 x2 = M4[e2 * 64 + f];
        float4 x3 = M4[e3 * 64 + f];
        float4 x4 = M4[e4 * 64 + f];
        float4 x5 = M4[e5 * 64 + f];
        float4 x6 = M4[e6 * 64 + f];
        float4 x7 = M4[e7 * 64 + f];
        acc.x += x0.x + x1.x + x2.x + x3.x;
        acc.y += x0.y + x1.y + x2.y + x3.y;
        acc.z += x0.z + x1.z + x2.z + x3.z;
        acc.w += x0.w + x1.w + x2.w + x3.w;
        acc.x += x4.x + x5.x + x6.x + x7.x;
        acc.y += x4.y + x5.y + x6.y + x7.y;
        acc.z += x4.z + x5.z + x6.z + x7.z;
        acc.w += x4.w + x5.w + x6.w + x7.w;
    }
    for (; j < je; ++j) {
        float4 x = M4[idx[j] * 64 + f];
        acc.x += x.x; acc.y += x.y; acc.z += x.z; acc.w += x.w;
    }

    red[t] = acc;
    __syncthreads();
    if (g == 0) {
        float4 a = red[half * 128 + f];
        float4 b = red[half * 128 + 64 + f];
        float dv = g_dvis[i];
        float4 bv = *(const float4*)&bias[f * 4];
        float4 o;
        o.x = fmaf(a.x + b.x, dv, bv.x);
        o.y = fmaf(a.y + b.y, dv, bv.y);
        o.z = fmaf(a.z + b.z, dv, bv.z);
        o.w = fmaf(a.w + b.w, dv, bv.w);
        *(float4*)&out[i * FF + f * 4] = o;
    }
}

// ============================================================
extern "C" void kernel_launch(void* const* d_in, const int* in_sizes, int n_in,
                              void* d_out, int out_size) {
    const float* X    = (const float*)d_in[0];   // [8192,256]
    const float* H    = (const float*)d_in[1];   // [8192,1024]
    const float* Wm   = (const float*)d_in[2];   // [256,256]
    const float* bias = (const float*)d_in[3];   // [256]
    float* out = (float*)d_out;

    pack_all   <<<NN / 32, 256>>>(H);
    edge_gather<<<EE, 256>>>(X);
    dim3 g1(FF / 64, EE / 128);
    gemm_mw    <<<g1, 256>>>(Wm);
    node_gather<<<NN / 2, 256>>>(bias, out);
}

// round 8
// speedup vs baseline: 1.1310x; 1.1310x over previous
#include <cuda_runtime.h>
#include <cstdint>

#define NN 8192
#define EE 1024
#define FF 256
#define NW (NN/32)   // 256 words per edge row (transposed bits)
#define EW (EE/32)   // 32 words per node row

// ---- scratch (no allocations allowed; device globals) ----
__device__ float    g_dvis[NN];                        // dv^{-1/2}
__device__ __align__(16) unsigned g_HbT[EE * NW];      // H^T bitpacked: [edge][node-word]
__device__ __align__(16) unsigned g_HbR[NN * EW];      // H bitpacked:   [node][edge-word]
__device__ __align__(16) float g_M [EE * FF];          // edge features
__device__ __align__(16) float g_MW[EE * FF];          // M @ W^T

// ============================================================
// One-pass pack: coalesced read of H -> HbR, HbT (bit transpose),
// dv^{-1/2}. CTA = 32 rows x 1024 cols.
// ============================================================
__global__ void __launch_bounds__(256) pack_all(const float* __restrict__ H) {
    const int r0 = blockIdx.x * 32;
    const int w  = threadIdx.x >> 5;
    const int l  = threadIdx.x & 31;

    __shared__ unsigned smask[32][32];

    int cnt[4] = {0, 0, 0, 0};
    for (int ch = 0; ch < 32; ++ch) {
        const int c0 = ch * 32;
        #pragma unroll
        for (int k = 0; k < 4; ++k) {
            const int row = w + 8 * k;
            float v = H[(long)(r0 + row) * EE + c0 + l];
            unsigned m = __ballot_sync(0xffffffffu, v != 0.f);
            cnt[k] += __popc(m);
            if (l == 0) {
                smask[ch][row] = m;
                g_HbR[(r0 + row) * EW + ch] = m;
            }
        }
    }
    if (l == 0) {
        #pragma unroll
        for (int k = 0; k < 4; ++k)
            g_dvis[r0 + w + 8 * k] = rsqrtf((float)cnt[k]);
    }
    __syncthreads();

    const int wordIdx = blockIdx.x;
    #pragma unroll
    for (int q = 0; q < 4; ++q) {
        const int cc = w + 8 * q;
        const unsigned rm = smask[cc][l];
        #pragma unroll
        for (int c = 0; c < 32; ++c) {
            unsigned colm = __ballot_sync(0xffffffffu, (rm >> c) & 1u);
            if (l == 0) g_HbT[(cc * 32 + c) * NW + wordIdx] = colm;
        }
    }
}

// ============================================================
// Pass A: M[e] = (1/de) * sum_{i in e} dvis[i] * X[i]
// 2 CTAs per edge (feature halves), 128 threads: 4 row-quarters
// x 32 lanes. uint2 mask decode, uint4 idx + float4 scale batches.
// ============================================================
#define MAX_DE 1024
__global__ void __launch_bounds__(128) edge_gather(const float* __restrict__ X) {
    const int e  = blockIdx.x >> 1;
    const int fh = blockIdx.x & 1;
    const int t  = threadIdx.x;
    const int lane = t & 31, wid = t >> 5;
    const int f = fh * 32 + lane;      // f4 column 0..63
    const int g = wid;                 // row quarter 0..3

    __shared__ __align__(16) unsigned short sidx[MAX_DE];
    __shared__ __align__(16) float          sdvv[MAX_DE];
    __shared__ int wtot[4];
    __shared__ int warpOff[5];
    __shared__ float4 red[128];

    // ---- decode: thread t owns mask words 2t, 2t+1 ----
    uint2 mw = *(const uint2*)&g_HbT[e * NW + 2 * t];
    int cnt = __popc(mw.x) + __popc(mw.y);
    int scan = cnt;
    #pragma unroll
    for (int o = 1; o < 32; o <<= 1) {
        int v = __shfl_up_sync(0xffffffffu, scan, o);
        if (lane >= o) scan += v;
    }
    if (lane == 31) wtot[wid] = scan;
    __syncthreads();
    if (t == 0) {
        int s = 0;
        #pragma unroll
        for (int w = 0; w < 4; ++w) { warpOff[w] = s; s += wtot[w]; }
        warpOff[4] = s;
    }
    __syncthreads();

    int off = warpOff[wid] + (scan - cnt);
    {
        unsigned m = mw.x;
        int base = t * 64;
        while (m) {
            int b = __ffs(m) - 1; m &= m - 1;
            int node = base + b;
            sidx[off] = (unsigned short)node;
            sdvv[off] = g_dvis[node];
            ++off;
        }
        m = mw.y;
        base += 32;
        while (m) {
            int b = __ffs(m) - 1; m &= m - 1;
            int node = base + b;
            sidx[off] = (unsigned short)node;
            sdvv[off] = g_dvis[node];
            ++off;
        }
    }
    __syncthreads();

    // ---- gather: contiguous quarter per warp, 8-aligned ----
    const int total = warpOff[4];
    const int Q  = ((total + 31) >> 5) << 3;   // ceil(total/4) to mult of 8
    const int jb = g * Q;
    const int je = min(jb + Q, total);

    const float4* X4 = (const float4*)X;
    float4 acc = make_float4(0.f, 0.f, 0.f, 0.f);

    int j = jb;
    for (; j + 8 <= je; j += 8) {
        uint4  iw = *(const uint4*)&sidx[j];
        float4 sa = *(const float4*)&sdvv[j];
        float4 sb = *(const float4*)&sdvv[j + 4];
        int n0 = iw.x & 0xffff, n1 = iw.x >> 16;
        int n2 = iw.y & 0xffff, n3 = iw.y >> 16;
        int n4 = iw.z & 0xffff, n5 = iw.z >> 16;
        int n6 = iw.w & 0xffff, n7 = iw.w >> 16;
        float4 x0 = X4[n0 * 64 + f];
        float4 x1 = X4[n1 * 64 + f];
        float4 x2 = X4[n2 * 64 + f];
        float4 x3 = X4[n3 * 64 + f];
        float4 x4 = X4[n4 * 64 + f];
        float4 x5 = X4[n5 * 64 + f];
        float4 x6 = X4[n6 * 64 + f];
        float4 x7 = X4[n7 * 64 + f];
        acc.x = fmaf(x0.x, sa.x, acc.x); acc.y = fmaf(x0.y, sa.x, acc.y);
        acc.z = fmaf(x0.z, sa.x, acc.z); acc.w = fmaf(x0.w, sa.x, acc.w);
        acc.x = fmaf(x1.x, sa.y, acc.x); acc.y = fmaf(x1.y, sa.y, acc.y);
        acc.z = fmaf(x1.z, sa.y, acc.z); acc.w = fmaf(x1.w, sa.y, acc.w);
        acc.x = fmaf(x2.x, sa.z, acc.x); acc.y = fmaf(x2.y, sa.z, acc.y);
        acc.z = fmaf(x2.z, sa.z, acc.z); acc.w = fmaf(x2.w, sa.z, acc.w);
        acc.x = fmaf(x3.x, sa.w, acc.x); acc.y = fmaf(x3.y, sa.w, acc.y);
        acc.z = fmaf(x3.z, sa.w, acc.z); acc.w = fmaf(x3.w, sa.w, acc.w);
        acc.x = fmaf(x4.x, sb.x, acc.x); acc.y = fmaf(x4.y, sb.x, acc.y);
        acc.z = fmaf(x4.z, sb.x, acc.z); acc.w = fmaf(x4.w, sb.x, acc.w);
        acc.x = fmaf(x5.x, sb.y, acc.x); acc.y = fmaf(x5.y, sb.y, acc.y);
        acc.z = fmaf(x5.z, sb.y, acc.z); acc.w = fmaf(x5.w, sb.y, acc.w);
        acc.x = fmaf(x6.x, sb.z, acc.x); acc.y = fmaf(x6.y, sb.z, acc.y);
        acc.z = fmaf(x6.z, sb.z, acc.z); acc.w = fmaf(x6.w, sb.z, acc.w);
        acc.x = fmaf(x7.x, sb.w, acc.x); acc.y = fmaf(x7.y, sb.w, acc.y);
        acc.z = fmaf(x7.z, sb.w, acc.z); acc.w = fmaf(x7.w, sb.w, acc.w);
    }
    for (; j < je; ++j) {
        int n = sidx[j]; float s = sdvv[j];
        float4 x = X4[n * 64 + f];
        acc.x = fmaf(x.x, s, acc.x); acc.y = fmaf(x.y, s, acc.y);
        acc.z = fmaf(x.z, s, acc.z); acc.w = fmaf(x.w, s, acc.w);
    }

    red[t] = acc;
    __syncthreads();
    if (g == 0) {
        float4 a = red[lane], b = red[lane + 32], c = red[lane + 64], d = red[lane + 96];
        float di = 1.f / (float)total;
        float4 o;
        o.x = (a.x + b.x + c.x + d.x) * di;
        o.y = (a.y + b.y + c.y + d.y) * di;
        o.z = (a.z + b.z + c.z + d.z) * di;
        o.w = (a.w + b.w + c.w + d.w) * di;
        *(float4*)&g_M[e * FF + f * 4] = o;
    }
}

// ============================================================
// g_MW = g_M @ W^T   ([1024,256] @ [256,256], both K-major)
// ============================================================
__global__ void __launch_bounds__(256) gemm_mw(const float* __restrict__ Wm) {
    __shared__ float As[32][128];
    __shared__ float Bs[32][64];

    const int tid = threadIdx.x;
    const int ty = tid >> 4;
    const int tx = tid & 15;
    const int i0 = blockIdx.y * 128;
    const int o0 = blockIdx.x * 64;

    float acc[8][4];
    #pragma unroll
    for (int r = 0; r < 8; ++r)
        #pragma unroll
        for (int c = 0; c < 4; ++c) acc[r][c] = 0.f;

    for (int kc = 0; kc < FF; kc += 32) {
        #pragma unroll
        for (int l = 0; l < 4; ++l) {
            int linear = tid + 256 * l;
            int i  = linear >> 3;
            int kq = (linear & 7) << 2;
            float4 v = *(const float4*)&g_M[(i0 + i) * FF + kc + kq];
            As[kq + 0][i] = v.x; As[kq + 1][i] = v.y;
            As[kq + 2][i] = v.z; As[kq + 3][i] = v.w;
        }
        #pragma unroll
        for (int l = 0; l < 2; ++l) {
            int linear = tid + 256 * l;
            int o  = linear >> 3;
            int kq = (linear & 7) << 2;
            float4 v = *(const float4*)&Wm[(o0 + o) * FF + kc + kq];
            Bs[kq + 0][o] = v.x; Bs[kq + 1][o] = v.y;
            Bs[kq + 2][o] = v.z; Bs[kq + 3][o] = v.w;
        }
        __syncthreads();
        #pragma unroll
        for (int kk = 0; kk < 32; ++kk) {
            float4 b4 = *(const float4*)&Bs[kk][tx * 4];
            float4 a0 = *(const float4*)&As[kk][ty * 8];
            float4 a1 = *(const float4*)&As[kk][ty * 8 + 4];
            float a[8] = {a0.x, a0.y, a0.z, a0.w, a1.x, a1.y, a1.z, a1.w};
            float bb[4] = {b4.x, b4.y, b4.z, b4.w};
            #pragma unroll
            for (int r = 0; r < 8; ++r)
                #pragma unroll
                for (int c = 0; c < 4; ++c)
                    acc[r][c] = fmaf(a[r], bb[c], acc[r][c]);
        }
        __syncthreads();
    }

    #pragma unroll
    for (int r = 0; r < 8; ++r) {
        int i = i0 + ty * 8 + r;
        float4 o4;
        o4.x = acc[r][0]; o4.y = acc[r][1];
        o4.z = acc[r][2]; o4.w = acc[r][3];
        *(float4*)&g_MW[i * FF + o0 + tx * 4] = o4;
    }
}

// ============================================================
// Pass B: out[i] = dvis[i] * sum_{e ni i} MW[e] + b
// 128-thread CTA, 2 nodes; 64 threads own a node's full column
// sum (NO cross-group reduction). uint4 idx batches, 8-deep MLP.
// ============================================================
#define MAX_DV 128
__global__ void __launch_bounds__(128) node_gather(const float* __restrict__ bias,
                                                   float* __restrict__ out) {
    const int t    = threadIdx.x;
    const int half = t >> 6;           // 0 or 1
    const int f    = t & 63;           // f4 column, also id within half
    const int i    = blockIdx.x * 2 + half;

    __shared__ __align__(16) unsigned short sidx[2][MAX_DV];
    __shared__ int stot[2];

    // decode: warp 0 -> half 0, warp 2 -> half 1
    if (f < 32) {
        unsigned m = g_HbR[i * EW + f];
        int cnt = __popc(m);
        int scan = cnt;
        #pragma unroll
        for (int o = 1; o < 32; o <<= 1) {
            int v = __shfl_up_sync(0xffffffffu, scan, o);
            if (f >= o) scan += v;
        }
        int off = scan - cnt;
        const int base = f * 32;
        while (m) {
            int b = __ffs(m) - 1; m &= m - 1;
            sidx[half][off++] = (unsigned short)(base + b);
        }
        if (f == 31) stot[half] = scan;
    }
    __syncthreads();

    const int total = stot[half];
    const unsigned short* idx = sidx[half];
    const float4* M4 = (const float4*)g_MW;
    float4 acc = make_float4(0.f, 0.f, 0.f, 0.f);

    int j = 0;
    for (; j + 8 <= total; j += 8) {
        uint4 iw = *(const uint4*)&idx[j];
        int e0 = iw.x & 0xffff, e1 = iw.x >> 16;
        int e2 = iw.y & 0xffff, e3 = iw.y >> 16;
        int e4 = iw.z & 0xffff, e5 = iw.z >> 16;
        int e6 = iw.w & 0xffff, e7 = iw.w >> 16;
        float4 x0 = M4[e0 * 64 + f];
        float4 x1 = M4[e1 * 64 + f];
        float4 x2 = M4[e2 * 64 + f];
        float4 x3 = M4[e3 * 64 + f];
        float4 x4 = M4[e4 * 64 + f];
        float4 x5 = M4[e5 * 64 + f];
        float4 x6 = M4[e6 * 64 + f];
        float4 x7 = M4[e7 * 64 + f];
        acc.x += x0.x + x1.x + x2.x + x3.x;
        acc.y += x0.y + x1.y + x2.y + x3.y;
        acc.z += x0.z + x1.z + x2.z + x3.z;
        acc.w += x0.w + x1.w + x2.w + x3.w;
        acc.x += x4.x + x5.x + x6.x + x7.x;
        acc.y += x4.y + x5.y + x6.y + x7.y;
        acc.z += x4.z + x5.z + x6.z + x7.z;
        acc.w += x4.w + x5.w + x6.w + x7.w;
    }
    for (; j < total; ++j) {
        float4 x = M4[idx[j] * 64 + f];
        acc.x += x.x; acc.y += x.y; acc.z += x.z; acc.w += x.w;
    }

    const float dv = g_dvis[i];
    float4 bv = *(const float4*)&bias[f * 4];
    float4 o;
    o.x = fmaf(acc.x, dv, bv.x);
    o.y = fmaf(acc.y, dv, bv.y);
    o.z = fmaf(acc.z, dv, bv.z);
    o.w = fmaf(acc.w, dv, bv.w);
    *(float4*)&out[i * FF + f * 4] = o;
}

// ============================================================
extern "C" void kernel_launch(void* const* d_in, const int* in_sizes, int n_in,
                              void* d_out, int out_size) {
    const float* X    = (const float*)d_in[0];   // [8192,256]
    const float* H    = (const float*)d_in[1];   // [8192,1024]
    const float* Wm   = (const float*)d_in[2];   // [256,256]
    const float* bias = (const float*)d_in[3];   // [256]
    float* out = (float*)d_out;

    pack_all   <<<NN / 32, 256>>>(H);
    edge_gather<<<EE * 2, 128>>>(X);
    dim3 g1(FF / 64, EE / 128);
    gemm_mw    <<<g1, 256>>>(Wm);
    node_gather<<<NN / 2, 128>>>(bias, out);
}

// round 9
// speedup vs baseline: 1.1314x; 1.0004x over previous
#include <cuda_runtime.h>
#include <cstdint>

#define NN 8192
#define EE 1024
#define FF 256
#define NW (NN/32)   // 256 words per edge row (transposed bits)
#define EW (EE/32)   // 32 words per node row

// ---- scratch (no allocations allowed; device globals) ----
__device__ float    g_dvis[NN];                        // dv^{-1/2}
__device__ __align__(16) unsigned g_HbT[EE * NW];      // H^T bitpacked: [edge][node-word]
__device__ __align__(16) unsigned g_HbR[NN * EW];      // H bitpacked:   [node][edge-word]
__device__ __align__(16) float g_Xs[NN * FF];          // dvis[i] * X[i]  (pre-scaled)
__device__ __align__(16) float g_M [EE * FF];          // edge features
__device__ __align__(16) float g_MW[EE * FF];          // M @ W^T

__device__ __forceinline__ float4 ldg_evl(const float4* p) {
    float4 v;
    asm volatile("ld.global.nc.L1::evict_last.v4.f32 {%0,%1,%2,%3}, [%4];"
        : "=f"(v.x), "=f"(v.y), "=f"(v.z), "=f"(v.w) : "l"(p));
    return v;
}

// ============================================================
// One-pass pack: coalesced read of H -> HbR, HbT (bit transpose),
// dv^{-1/2}, and pre-scaled Xs = dvis*X. CTA = 32 rows.
// ============================================================
__global__ void __launch_bounds__(256) pack_all(const float* __restrict__ H,
                                                const float* __restrict__ X) {
    const int r0 = blockIdx.x * 32;
    const int w  = threadIdx.x >> 5;
    const int l  = threadIdx.x & 31;
    const int tid = threadIdx.x;

    __shared__ unsigned smask[32][32];
    __shared__ float sdvr[32];

    int cnt[4] = {0, 0, 0, 0};
    for (int ch = 0; ch < 32; ++ch) {
        const int c0 = ch * 32;
        #pragma unroll
        for (int k = 0; k < 4; ++k) {
            const int row = w + 8 * k;
            float v = H[(long)(r0 + row) * EE + c0 + l];
            unsigned m = __ballot_sync(0xffffffffu, v != 0.f);
            cnt[k] += __popc(m);
            if (l == 0) {
                smask[ch][row] = m;
                g_HbR[(r0 + row) * EW + ch] = m;
            }
        }
    }
    if (l == 0) {
        #pragma unroll
        for (int k = 0; k < 4; ++k) {
            float dv = rsqrtf((float)cnt[k]);
            g_dvis[r0 + w + 8 * k] = dv;
            sdvr[w + 8 * k] = dv;
        }
    }
    __syncthreads();

    // bit transpose -> HbT
    const int wordIdx = blockIdx.x;
    #pragma unroll
    for (int q = 0; q < 4; ++q) {
        const int cc = w + 8 * q;
        const unsigned rm = smask[cc][l];
        #pragma unroll
        for (int c = 0; c < 32; ++c) {
            unsigned colm = __ballot_sync(0xffffffffu, (rm >> c) & 1u);
            if (l == 0) g_HbT[(cc * 32 + c) * NW + wordIdx] = colm;
        }
    }

    // Xs = dvis * X for these 32 rows (coalesced float4)
    const float4* X4  = (const float4*)X;
    float4*       Xs4 = (float4*)g_Xs;
    #pragma unroll
    for (int u = 0; u < 8; ++u) {
        int idx = tid + 256 * u;         // 0..2047
        int row = idx >> 6;              // 64 float4 per row
        int col = idx & 63;
        float dv = sdvr[row];
        float4 x = X4[(long)(r0 + row) * 64 + col];
        float4 o;
        o.x = x.x * dv; o.y = x.y * dv; o.z = x.z * dv; o.w = x.w * dv;
        Xs4[(long)(r0 + row) * 64 + col] = o;
    }
}

// ============================================================
// Pass A: M[e] = (1/de) * sum_{i in e} Xs[i]
// 2 CTAs per edge (feature halves), 128 threads: 4 row-quarters
// x 32 lanes. uint2 mask decode, uint4 idx batches, plain adds.
// ============================================================
#define MAX_DE 1024
__global__ void __launch_bounds__(128) edge_gather() {
    const int e  = blockIdx.x >> 1;
    const int fh = blockIdx.x & 1;
    const int t  = threadIdx.x;
    const int lane = t & 31, wid = t >> 5;
    const int f = fh * 32 + lane;      // f4 column 0..63
    const int g = wid;                 // row quarter 0..3

    __shared__ __align__(16) unsigned short sidx[MAX_DE];
    __shared__ int wtot[4];
    __shared__ int warpOff[5];
    __shared__ float4 red[128];

    // ---- decode: thread t owns mask words 2t, 2t+1 ----
    uint2 mw = *(const uint2*)&g_HbT[e * NW + 2 * t];
    int cnt = __popc(mw.x) + __popc(mw.y);
    int scan = cnt;
    #pragma unroll
    for (int o = 1; o < 32; o <<= 1) {
        int v = __shfl_up_sync(0xffffffffu, scan, o);
        if (lane >= o) scan += v;
    }
    if (lane == 31) wtot[wid] = scan;
    __syncthreads();
    if (t == 0) {
        int s = 0;
        #pragma unroll
        for (int w = 0; w < 4; ++w) { warpOff[w] = s; s += wtot[w]; }
        warpOff[4] = s;
    }
    __syncthreads();

    int off = warpOff[wid] + (scan - cnt);
    {
        unsigned m = mw.x;
        int base = t * 64;
        while (m) {
            int b = __ffs(m) - 1; m &= m - 1;
            sidx[off++] = (unsigned short)(base + b);
        }
        m = mw.y;
        base += 32;
        while (m) {
            int b = __ffs(m) - 1; m &= m - 1;
            sidx[off++] = (unsigned short)(base + b);
        }
    }
    __syncthreads();

    // ---- gather: contiguous quarter per warp, 8-aligned ----
    const int total = warpOff[4];
    const int Q  = ((total + 31) >> 5) << 3;
    const int jb = g * Q;
    const int je = min(jb + Q, total);

    const float4* X4 = (const float4*)g_Xs;
    float4 acc = make_float4(0.f, 0.f, 0.f, 0.f);

    int j = jb;
    for (; j + 8 <= je; j += 8) {
        uint4 iw = *(const uint4*)&sidx[j];
        int n0 = iw.x & 0xffff, n1 = iw.x >> 16;
        int n2 = iw.y & 0xffff, n3 = iw.y >> 16;
        int n4 = iw.z & 0xffff, n5 = iw.z >> 16;
        int n6 = iw.w & 0xffff, n7 = iw.w >> 16;
        float4 x0 = X4[n0 * 64 + f];
        float4 x1 = X4[n1 * 64 + f];
        float4 x2 = X4[n2 * 64 + f];
        float4 x3 = X4[n3 * 64 + f];
        float4 x4 = X4[n4 * 64 + f];
        float4 x5 = X4[n5 * 64 + f];
        float4 x6 = X4[n6 * 64 + f];
        float4 x7 = X4[n7 * 64 + f];
        acc.x += x0.x + x1.x + x2.x + x3.x;
        acc.y += x0.y + x1.y + x2.y + x3.y;
        acc.z += x0.z + x1.z + x2.z + x3.z;
        acc.w += x0.w + x1.w + x2.w + x3.w;
        acc.x += x4.x + x5.x + x6.x + x7.x;
        acc.y += x4.y + x5.y + x6.y + x7.y;
        acc.z += x4.z + x5.z + x6.z + x7.z;
        acc.w += x4.w + x5.w + x6.w + x7.w;
    }
    for (; j < je; ++j) {
        float4 x = X4[sidx[j] * 64 + f];
        acc.x += x.x; acc.y += x.y; acc.z += x.z; acc.w += x.w;
    }

    red[t] = acc;
    __syncthreads();
    if (g == 0) {
        float4 a = red[lane], b = red[lane + 32], c = red[lane + 64], d = red[lane + 96];
        float di = 1.f / (float)total;
        float4 o;
        o.x = (a.x + b.x + c.x + d.x) * di;
        o.y = (a.y + b.y + c.y + d.y) * di;
        o.z = (a.z + b.z + c.z + d.z) * di;
        o.w = (a.w + b.w + c.w + d.w) * di;
        *(float4*)&g_M[e * FF + f * 4] = o;
    }
}

// ============================================================
// g_MW = g_M @ W^T   ([1024,256] @ [256,256], both K-major)
// ============================================================
__global__ void __launch_bounds__(256) gemm_mw(const float* __restrict__ Wm) {
    __shared__ float As[32][128];
    __shared__ float Bs[32][64];

    const int tid = threadIdx.x;
    const int ty = tid >> 4;
    const int tx = tid & 15;
    const int i0 = blockIdx.y * 128;
    const int o0 = blockIdx.x * 64;

    float acc[8][4];
    #pragma unroll
    for (int r = 0; r < 8; ++r)
        #pragma unroll
        for (int c = 0; c < 4; ++c) acc[r][c] = 0.f;

    for (int kc = 0; kc < FF; kc += 32) {
        #pragma unroll
        for (int l = 0; l < 4; ++l) {
            int linear = tid + 256 * l;
            int i  = linear >> 3;
            int kq = (linear & 7) << 2;
            float4 v = *(const float4*)&g_M[(i0 + i) * FF + kc + kq];
            As[kq + 0][i] = v.x; As[kq + 1][i] = v.y;
            As[kq + 2][i] = v.z; As[kq + 3][i] = v.w;
        }
        #pragma unroll
        for (int l = 0; l < 2; ++l) {
            int linear = tid + 256 * l;
            int o  = linear >> 3;
            int kq = (linear & 7) << 2;
            float4 v = *(const float4*)&Wm[(o0 + o) * FF + kc + kq];
            Bs[kq + 0][o] = v.x; Bs[kq + 1][o] = v.y;
            Bs[kq + 2][o] = v.z; Bs[kq + 3][o] = v.w;
        }
        __syncthreads();
        #pragma unroll
        for (int kk = 0; kk < 32; ++kk) {
            float4 b4 = *(const float4*)&Bs[kk][tx * 4];
            float4 a0 = *(const float4*)&As[kk][ty * 8];
            float4 a1 = *(const float4*)&As[kk][ty * 8 + 4];
            float a[8] = {a0.x, a0.y, a0.z, a0.w, a1.x, a1.y, a1.z, a1.w};
            float bb[4] = {b4.x, b4.y, b4.z, b4.w};
            #pragma unroll
            for (int r = 0; r < 8; ++r)
                #pragma unroll
                for (int c = 0; c < 4; ++c)
                    acc[r][c] = fmaf(a[r], bb[c], acc[r][c]);
        }
        __syncthreads();
    }

    #pragma unroll
    for (int r = 0; r < 8; ++r) {
        int i = i0 + ty * 8 + r;
        float4 o4;
        o4.x = acc[r][0]; o4.y = acc[r][1];
        o4.z = acc[r][2]; o4.w = acc[r][3];
        *(float4*)&g_MW[i * FF + o0 + tx * 4] = o4;
    }
}

// ============================================================
// Pass B: out[i] = dvis[i] * sum_{e ni i} MW[e] + b
// 128-thread CTA, 2 nodes; 64 threads own a node's full column
// sum. uint4 idx batches, 8-deep MLP, evict_last on MW loads.
// ============================================================
#define MAX_DV 128
__global__ void __launch_bounds__(128) node_gather(const float* __restrict__ bias,
                                                   float* __restrict__ out) {
    const int t    = threadIdx.x;
    const int half = t >> 6;           // 0 or 1
    const int f    = t & 63;           // f4 column, also id within half
    const int i    = blockIdx.x * 2 + half;

    __shared__ __align__(16) unsigned short sidx[2][MAX_DV];
    __shared__ int stot[2];

    if (f < 32) {
        unsigned m = g_HbR[i * EW + f];
        int cnt = __popc(m);
        int scan = cnt;
        #pragma unroll
        for (int o = 1; o < 32; o <<= 1) {
            int v = __shfl_up_sync(0xffffffffu, scan, o);
            if (f >= o) scan += v;
        }
        int off = scan - cnt;
        const int base = f * 32;
        while (m) {
            int b = __ffs(m) - 1; m &= m - 1;
            sidx[half][off++] = (unsigned short)(base + b);
        }
        if (f == 31) stot[half] = scan;
    }
    __syncthreads();

    const int total = stot[half];
    const unsigned short* idx = sidx[half];
    const float4* M4 = (const float4*)g_MW;
    float4 acc = make_float4(0.f, 0.f, 0.f, 0.f);

    int j = 0;
    for (; j + 8 <= total; j += 8) {
        uint4 iw = *(const uint4*)&idx[j];
        int e0 = iw.x & 0xffff, e1 = iw.x >> 16;
        int e2 = iw.y & 0xffff, e3 = iw.y >> 16;
        int e4 = iw.z & 0xffff, e5 = iw.z >> 16;
        int e6 = iw.w & 0xffff, e7 = iw.w >> 16;
        float4 x0 = ldg_evl(&M4[e0 * 64 + f]);
        float4 x1 = ldg_evl(&M4[e1 * 64 + f]);
        float4 x2 = ldg_evl(&M4[e2 * 64 + f]);
        float4 x3 = ldg_evl(&M4[e3 * 64 + f]);
        float4 x4 = ldg_evl(&M4[e4 * 64 + f]);
        float4 x5 = ldg_evl(&M4[e5 * 64 + f]);
        float4 x6 = ldg_evl(&M4[e6 * 64 + f]);
        float4 x7 = ldg_evl(&M4[e7 * 64 + f]);
        acc.x += x0.x + x1.x + x2.x + x3.x;
        acc.y += x0.y + x1.y + x2.y + x3.y;
        acc.z += x0.z + x1.z + x2.z + x3.z;
        acc.w += x0.w + x1.w + x2.w + x3.w;
        acc.x += x4.x + x5.x + x6.x + x7.x;
        acc.y += x4.y + x5.y + x6.y + x7.y;
        acc.z += x4.z + x5.z + x6.z + x7.z;
        acc.w += x4.w + x5.w + x6.w + x7.w;
    }
    for (; j < total; ++j) {
        float4 x = ldg_evl(&M4[idx[j] * 64 + f]);
        acc.x += x.x; acc.y += x.y; acc.z += x.z; acc.w += x.w;
    }

    const float dv = g_dvis[i];
    float4 bv = *(const float4*)&bias[f * 4];
    float4 o;
    o.x = fmaf(acc.x, dv, bv.x);
    o.y = fmaf(acc.y, dv, bv.y);
    o.z = fmaf(acc.z, dv, bv.z);
    o.w = fmaf(acc.w, dv, bv.w);
    *(float4*)&out[i * FF + f * 4] = o;
}

// ============================================================
extern "C" void kernel_launch(void* const* d_in, const int* in_sizes, int n_in,
                              void* d_out, int out_size) {
    const float* X    = (const float*)d_in[0];   // [8192,256]
    const float* H    = (const float*)d_in[1];   // [8192,1024]
    const float* Wm   = (const float*)d_in[2];   // [256,256]
    const float* bias = (const float*)d_in[3];   // [256]
    float* out = (float*)d_out;

    pack_all   <<<NN / 32, 256>>>(H, X);
    edge_gather<<<EE * 2, 128>>>();
    dim3 g1(FF / 64, EE / 128);
    gemm_mw    <<<g1, 256>>>(Wm);
    node_gather<<<NN / 2, 128>>>(bias, out);
}